// round 2
// baseline (speedup 1.0000x reference)
#include <cuda_runtime.h>
#include <cuda_bf16.h>
#include <math.h>

#define EMB 128
#define NPRICE 100
#define NCAT 1000
#define BATCH 4096
#define SEQL 50

// Precomputed conv table: C[p][w][e] = sum_i E[p,i] * conv_w[e,i,w]
__device__ float g_C[NPRICE * 3 * EMB];

// ---------------------------------------------------------------------------
// Kernel 1: precompute C.  grid = NPRICE blocks, 128 threads (one per out ch)
// ---------------------------------------------------------------------------
__global__ void precompute_C_kernel(const float* __restrict__ PE,
                                    const float* __restrict__ CW) {
    const int p = blockIdx.x;
    const int o = threadIdx.x;
    __shared__ float sE[EMB];
    sE[o] = PE[p * EMB + o];
    __syncthreads();

    float a0 = 0.f, a1 = 0.f, a2 = 0.f;
    const float* w = CW + o * (EMB * 3);   // conv_w[o, i, w] row
#pragma unroll 8
    for (int i = 0; i < EMB; i++) {
        const float e = sE[i];
        a0 = fmaf(e, __ldg(&w[i * 3 + 0]), a0);
        a1 = fmaf(e, __ldg(&w[i * 3 + 1]), a1);
        a2 = fmaf(e, __ldg(&w[i * 3 + 2]), a2);
    }
    g_C[(p * 3 + 0) * EMB + o] = a0;
    g_C[(p * 3 + 1) * EMB + o] = a1;
    g_C[(p * 3 + 2) * EMB + o] = a2;
}

// ---------------------------------------------------------------------------
// Kernel 2: sensitivity.  1 block, 128 threads.
// ---------------------------------------------------------------------------
__global__ void sensitivity_kernel(const float* __restrict__ PE,
                                   const float* __restrict__ CE,
                                   const float* __restrict__ GW,
                                   const float* __restrict__ GB,
                                   float* __restrict__ out) {
    __shared__ float stats[3 * EMB];
    const int e = threadIdx.x;

    float s = 0.f, sq = 0.f;
#pragma unroll 4
    for (int p = 0; p < NPRICE; p++) {
        const float v = PE[p * EMB + e];
        s += v;
        sq = fmaf(v, v, sq);
    }
    const float mean = s * (1.f / NPRICE);
    float var = (sq - (float)NPRICE * mean * mean) * (1.f / (NPRICE - 1));
    var = fmaxf(var, 0.f);
    stats[e] = mean;
    stats[EMB + e] = sqrtf(var);

    float cs = 0.f;
#pragma unroll 4
    for (int p = 0; p < NCAT; p++) cs += CE[p * EMB + e];
    stats[2 * EMB + e] = cs * (1.f / NCAT);
    __syncthreads();

    float acc = GB[e];
    const float* w = GW + e * (3 * EMB);
#pragma unroll 8
    for (int j = 0; j < 3 * EMB; j++) acc = fmaf(stats[j], w[j], acc);
    out[e] = 1.f / (1.f + expf(-acc));
}

// ---------------------------------------------------------------------------
// Kernel 3: main trend kernel.  grid = BATCH blocks, 128 threads (one per ch)
// ---------------------------------------------------------------------------
#define CPAD 129   // padded row stride for conv tile (bank-conflict free both ways)

__global__ __launch_bounds__(EMB) void trend_kernel(
    const int* __restrict__ seqs,         // [B, L] int32 (JAX x64 disabled)
    const int* __restrict__ mask,         // [B, L] int32
    const float* __restrict__ PE,         // [NPRICE, EMB]
    const float* __restrict__ CB,         // conv bias [EMB]
    const float* __restrict__ AW,         // attn_w [1, EMB]
    float* __restrict__ trend)            // [B, EMB]
{
    const int b = blockIdx.x;
    const int e = threadIdx.x;

    __shared__ int   s_idx[SEQL];
    __shared__ float s_aw[EMB];
    __shared__ float s_conv[SEQL * CPAD];
    __shared__ float s_sc[SEQL];
    __shared__ int   s_valid;
    __shared__ float s_inv;

    if (e == 0) s_valid = 0;
    s_aw[e] = AW[e];

    // load clipped indices (threads 0..49) and mask sum
    int mv = 0;
    if (e < SEQL) {
        int iv = seqs[b * SEQL + e];
        iv = min(max(iv, 0), NPRICE - 1);
        s_idx[e] = iv;
        mv = mask[b * SEQL + e];
    }
    __syncthreads();   // s_valid=0 visible before atomics

#pragma unroll
    for (int off = 16; off; off >>= 1)
        mv += __shfl_down_sync(0xffffffffu, mv, off);
    if ((e & 31) == 0 && mv) atomicAdd(&s_valid, mv);
    __syncthreads();

    const int valid = s_valid;
    if (valid == 0) {                       // uniform across CTA
        trend[b * EMB + e] = 0.f;
        return;
    }
    if (valid < 3) {                        // short branch: plain mean pool
        float acc = 0.f;
#pragma unroll 5
        for (int l = 0; l < SEQL; l++) acc += PE[s_idx[l] * EMB + e];
        trend[b * EMB + e] = acc * (1.f / SEQL);
        return;
    }

    // long branch: conv(gathered) = table lookups, relu, attn softmax pool
    const float bias = CB[e];
    {
        float c = bias + g_C[(s_idx[0] * 3 + 1) * EMB + e]
                       + g_C[(s_idx[1] * 3 + 2) * EMB + e];
        s_conv[0 * CPAD + e] = fmaxf(c, 0.f);
    }
#pragma unroll 4
    for (int l = 1; l < SEQL - 1; l++) {
        float c = bias + g_C[(s_idx[l - 1] * 3 + 0) * EMB + e]
                       + g_C[(s_idx[l    ] * 3 + 1) * EMB + e]
                       + g_C[(s_idx[l + 1] * 3 + 2) * EMB + e];
        s_conv[l * CPAD + e] = fmaxf(c, 0.f);
    }
    {
        float c = bias + g_C[(s_idx[SEQL - 2] * 3 + 0) * EMB + e]
                       + g_C[(s_idx[SEQL - 1] * 3 + 1) * EMB + e];
        s_conv[(SEQL - 1) * CPAD + e] = fmaxf(c, 0.f);
    }
    __syncthreads();

    // attention scores: thread l (<50) does dot(conv[l,:], attn_w)
    if (e < SEQL) {
        float sacc = 0.f;
        const float* row = &s_conv[e * CPAD];
#pragma unroll 8
        for (int j = 0; j < EMB; j++) sacc = fmaf(row[j], s_aw[j], sacc);
        s_sc[e] = sacc;
    }
    __syncthreads();

    // softmax over 50 (serial on thread 0 — tiny)
    if (e == 0) {
        float mx = -1e30f;
#pragma unroll 5
        for (int l = 0; l < SEQL; l++) mx = fmaxf(mx, s_sc[l]);
        float sum = 0.f;
#pragma unroll 5
        for (int l = 0; l < SEQL; l++) {
            const float w = expf(s_sc[l] - mx);
            s_sc[l] = w;
            sum += w;
        }
        s_inv = 1.f / sum;
    }
    __syncthreads();

    const float inv = s_inv;
    float acc = 0.f;
#pragma unroll 5
    for (int l = 0; l < SEQL; l++)
        acc = fmaf(s_conv[l * CPAD + e], s_sc[l] * inv, acc);
    trend[b * EMB + e] = acc;
}

// ---------------------------------------------------------------------------
// launch
// ---------------------------------------------------------------------------
extern "C" void kernel_launch(void* const* d_in, const int* in_sizes, int n_in,
                              void* d_out, int out_size) {
    const float* price_emb  = (const float*)d_in[0];      // [100,128]
    const int*   price_seqs = (const int*)d_in[1];        // [4096,50] int32
    const float* cat_emb    = (const float*)d_in[2];      // [1000,128]
    const int*   sess_mask  = (const int*)d_in[3];        // [4096,50] int32
    const float* gate_w     = (const float*)d_in[4];      // [128,384]
    const float* gate_b     = (const float*)d_in[5];      // [128]
    const float* conv_w     = (const float*)d_in[6];      // [128,128,3]
    const float* conv_b     = (const float*)d_in[7];      // [128]
    const float* attn_w     = (const float*)d_in[8];      // [1,128]
    // attn_b (d_in[9]) cancels inside softmax — unused.

    float* out = (float*)d_out;
    float* sens_out  = out;          // first 128 floats
    float* trend_out = out + EMB;    // [4096,128]

    precompute_C_kernel<<<NPRICE, EMB>>>(price_emb, conv_w);
    sensitivity_kernel<<<1, EMB>>>(price_emb, cat_emb, gate_w, gate_b, sens_out);
    trend_kernel<<<BATCH, EMB>>>(price_seqs, sess_mask, price_emb,
                                 conv_b, attn_w, trend_out);
}

// round 3
// speedup vs baseline: 2.0277x; 2.0277x over previous
#include <cuda_runtime.h>
#include <cuda_bf16.h>
#include <math.h>

#define EMB 128
#define NPRICE 100
#define NCAT 1000
#define BATCH 4096
#define SEQL 50

// Conv table with sentinel zero row at p=NPRICE:
//   g_C[(p*3+w)*EMB + o] ;  C1 has conv_b folded in.
__device__ float g_C[(NPRICE + 1) * 3 * EMB];
// Transposed conv weights: g_WT[w*EMB*EMB + i*EMB + o]
__device__ float g_WT[3 * EMB * EMB];
// Category-embedding column partial sums: [25][EMB]
#define NCATBLK 25
__device__ float g_catpart[NCATBLK * EMB];

// ---------------------------------------------------------------------------
// Kernel 1: fused (a) CE column partial sums (blocks 0..24),
//                 (b) conv_w transpose (blocks 25..72)
// 1024 threads per block.
// ---------------------------------------------------------------------------
__global__ __launch_bounds__(1024) void prep_kernel(
    const float* __restrict__ CE,   // [NCAT, EMB]
    const float* __restrict__ CW)   // [EMB, EMB, 3]
{
    const int tid = threadIdx.x;
    if (blockIdx.x < NCATBLK) {
        // --- CE partial sums: rows [40j, 40j+40) ---
        const int j = blockIdx.x;
        const int e = tid & (EMB - 1);
        const int r = tid >> 7;             // 0..7
        __shared__ float s_acc[8][EMB];
        float acc = 0.f;
#pragma unroll
        for (int k = 0; k < 5; k++) {
            const int p = j * 40 + r + k * 8;
            acc += CE[p * EMB + e];
        }
        s_acc[r][e] = acc;
        __syncthreads();
        if (r == 0) {
            float t = 0.f;
#pragma unroll
            for (int q = 0; q < 8; q++) t += s_acc[q][e];
            g_catpart[j * EMB + e] = t;
        }
    } else {
        // --- transpose: 48 blocks x 1024 = 49152 elements ---
        const int idx = (blockIdx.x - NCATBLK) * 1024 + tid;  // < 3*EMB*EMB
        const int o = idx / (EMB * 3);
        const int rem = idx - o * (EMB * 3);
        const int i = rem / 3;
        const int w = rem - i * 3;
        g_WT[w * (EMB * EMB) + i * EMB + o] = CW[idx];
    }
}

// ---------------------------------------------------------------------------
// Kernel 2: fused (a) C-table build (blocks 0..99), (b) sentinel zero
//           (block 100), (c) sensitivity (block 101). 128 threads.
// ---------------------------------------------------------------------------
__global__ __launch_bounds__(EMB) void build_kernel(
    const float* __restrict__ PE,   // [NPRICE, EMB]
    const float* __restrict__ CB,   // conv bias [EMB]
    const float* __restrict__ GW,   // gate_w [EMB, 3*EMB]
    const float* __restrict__ GB,   // gate_b [EMB]
    float* __restrict__ sens_out)   // [EMB]
{
    const int o = threadIdx.x;
    if (blockIdx.x < NPRICE) {
        const int p = blockIdx.x;
        __shared__ float sE[EMB];
        sE[o] = PE[p * EMB + o];
        __syncthreads();
        float a0 = 0.f, a1 = 0.f, a2 = 0.f;
#pragma unroll 8
        for (int i = 0; i < EMB; i++) {
            const float e = sE[i];
            a0 = fmaf(e, g_WT[0 * (EMB * EMB) + i * EMB + o], a0);
            a1 = fmaf(e, g_WT[1 * (EMB * EMB) + i * EMB + o], a1);
            a2 = fmaf(e, g_WT[2 * (EMB * EMB) + i * EMB + o], a2);
        }
        g_C[(p * 3 + 0) * EMB + o] = a0;
        g_C[(p * 3 + 1) * EMB + o] = a1 + CB[o];   // bias folded into C1
        g_C[(p * 3 + 2) * EMB + o] = a2;
    } else if (blockIdx.x == NPRICE) {
        // sentinel zero row
        g_C[(NPRICE * 3 + 0) * EMB + o] = 0.f;
        g_C[(NPRICE * 3 + 1) * EMB + o] = 0.f;
        g_C[(NPRICE * 3 + 2) * EMB + o] = 0.f;
    } else {
        // sensitivity
        __shared__ float stats[3 * EMB];
        float s = 0.f, sq = 0.f;
#pragma unroll 10
        for (int p = 0; p < NPRICE; p++) {
            const float v = PE[p * EMB + o];
            s += v;
            sq = fmaf(v, v, sq);
        }
        const float mean = s * (1.f / NPRICE);
        float var = (sq - (float)NPRICE * mean * mean) * (1.f / (NPRICE - 1));
        var = fmaxf(var, 0.f);
        stats[o] = mean;
        stats[EMB + o] = sqrtf(var);

        float cs = 0.f;
#pragma unroll
        for (int j = 0; j < NCATBLK; j++) cs += g_catpart[j * EMB + o];
        stats[2 * EMB + o] = cs * (1.f / NCAT);
        __syncthreads();

        float acc = GB[o];
        const float* w = GW + o * (3 * EMB);
#pragma unroll 8
        for (int j = 0; j < 3 * EMB; j++) acc = fmaf(stats[j], w[j], acc);
        sens_out[o] = 1.f / (1.f + expf(-acc));
    }
}

// ---------------------------------------------------------------------------
// Kernel 3: trend. grid = BATCH, 128 threads (one per channel).
// conv held in registers; scores via warp butterfly + 4-way smem combine.
// ---------------------------------------------------------------------------
__global__ __launch_bounds__(EMB) void trend_kernel(
    const int* __restrict__ seqs,         // [B, L] int32
    const int* __restrict__ mask,         // [B, L] int32
    const float* __restrict__ PE,         // [NPRICE, EMB]
    const float* __restrict__ AW,         // attn_w [1, EMB]
    float* __restrict__ trend)            // [B, EMB]
{
    const int b = blockIdx.x;
    const int e = threadIdx.x;
    const int warp = e >> 5;
    const int lane = e & 31;

    __shared__ int   s_idx[SEQL + 2];     // shifted: [0]=sent, [1..50]=idx, [51]=sent
    __shared__ float s_part[SEQL * 4];
    __shared__ float s_sc[SEQL];
    __shared__ int   s_valid;
    __shared__ float s_inv;

    if (e == 0) { s_valid = 0; s_idx[0] = NPRICE; s_idx[SEQL + 1] = NPRICE; }

    int mv = 0;
    if (e < SEQL) {
        int iv = seqs[b * SEQL + e];
        iv = min(max(iv, 0), NPRICE - 1);
        s_idx[e + 1] = iv;
        mv = mask[b * SEQL + e];
    }
    __syncthreads();

#pragma unroll
    for (int off = 16; off; off >>= 1)
        mv += __shfl_down_sync(0xffffffffu, mv, off);
    if (lane == 0 && mv) atomicAdd(&s_valid, mv);
    __syncthreads();

    const int valid = s_valid;
    if (valid == 0) {
        trend[b * EMB + e] = 0.f;
        return;
    }
    if (valid < 3) {
        float acc = 0.f;
#pragma unroll 10
        for (int l = 0; l < SEQL; l++) acc += PE[s_idx[l + 1] * EMB + e];
        trend[b * EMB + e] = acc * (1.f / SEQL);
        return;
    }

    // conv in registers (C1 carries the bias; sentinel rows are zero)
    const float aw = AW[e];
    float conv[SEQL];
#pragma unroll
    for (int l = 0; l < SEQL; l++) {
        float c = g_C[(s_idx[l    ] * 3 + 0) * EMB + e]
                + g_C[(s_idx[l + 1] * 3 + 1) * EMB + e]
                + g_C[(s_idx[l + 2] * 3 + 2) * EMB + e];
        conv[l] = fmaxf(c, 0.f);
    }

    // attention scores: per-l warp butterfly, 4-way combine in smem
#pragma unroll
    for (int l = 0; l < SEQL; l++) {
        float v = conv[l] * aw;
#pragma unroll
        for (int off = 16; off; off >>= 1)
            v += __shfl_xor_sync(0xffffffffu, v, off);
        if (lane == 0) s_part[l * 4 + warp] = v;
    }
    __syncthreads();
    if (e < SEQL)
        s_sc[e] = s_part[e * 4] + s_part[e * 4 + 1] + s_part[e * 4 + 2] + s_part[e * 4 + 3];
    __syncthreads();

    if (e == 0) {
        float mx = -1e30f;
#pragma unroll 10
        for (int l = 0; l < SEQL; l++) mx = fmaxf(mx, s_sc[l]);
        float sum = 0.f;
#pragma unroll 10
        for (int l = 0; l < SEQL; l++) {
            const float w = expf(s_sc[l] - mx);
            s_sc[l] = w;
            sum += w;
        }
        s_inv = 1.f / sum;
    }
    __syncthreads();

    const float inv = s_inv;
    float acc = 0.f;
#pragma unroll
    for (int l = 0; l < SEQL; l++)
        acc = fmaf(conv[l], s_sc[l], acc);
    trend[b * EMB + e] = acc * inv;
}

// ---------------------------------------------------------------------------
// launch
// ---------------------------------------------------------------------------
extern "C" void kernel_launch(void* const* d_in, const int* in_sizes, int n_in,
                              void* d_out, int out_size) {
    const float* price_emb  = (const float*)d_in[0];      // [100,128]
    const int*   price_seqs = (const int*)d_in[1];        // [4096,50] int32
    const float* cat_emb    = (const float*)d_in[2];      // [1000,128]
    const int*   sess_mask  = (const int*)d_in[3];        // [4096,50] int32
    const float* gate_w     = (const float*)d_in[4];      // [128,384]
    const float* gate_b     = (const float*)d_in[5];      // [128]
    const float* conv_w     = (const float*)d_in[6];      // [128,128,3]
    const float* conv_b     = (const float*)d_in[7];      // [128]
    const float* attn_w     = (const float*)d_in[8];      // [1,128]
    // attn_b (d_in[9]) cancels inside softmax — unused.

    float* out = (float*)d_out;
    float* sens_out  = out;          // first 128 floats
    float* trend_out = out + EMB;    // [4096,128]

    prep_kernel<<<NCATBLK + 48, 1024>>>(cat_emb, conv_w);
    build_kernel<<<NPRICE + 2, EMB>>>(price_emb, conv_b, gate_w, gate_b, sens_out);
    trend_kernel<<<BATCH, EMB>>>(price_seqs, sess_mask, price_emb,
                                 attn_w, trend_out);
}

// round 4
// speedup vs baseline: 2.9423x; 1.4511x over previous
#include <cuda_runtime.h>
#include <cuda_bf16.h>
#include <math.h>

#define EMB 128
#define NPRICE 100
#define NCAT 1000
#define BATCH 4096
#define SEQL 50
#define ROW_BYTES (3 * EMB * 4)      // 1536 bytes per price entry in g_C

// Conv table with sentinel zero row at p=NPRICE:
//   layout: g_C[p][w][o] ; C1 (w=1) has conv_b folded in.
__device__ float g_C[(NPRICE + 1) * 3 * EMB];
// Transposed conv weights: g_WT[w*EMB*EMB + i*EMB + o]
__device__ float g_WT[3 * EMB * EMB];
// Category-embedding column partial sums: [25][EMB]
#define NCATBLK 25
__device__ float g_catpart[NCATBLK * EMB];

// ---------------------------------------------------------------------------
// Kernel 1: fused (a) CE column partial sums (blocks 0..24),
//                 (b) conv_w transpose (blocks 25..72). 1024 threads.
// ---------------------------------------------------------------------------
__global__ __launch_bounds__(1024) void prep_kernel(
    const float* __restrict__ CE,   // [NCAT, EMB]
    const float* __restrict__ CW)   // [EMB, EMB, 3]
{
    const int tid = threadIdx.x;
    if (blockIdx.x < NCATBLK) {
        const int j = blockIdx.x;
        const int e = tid & (EMB - 1);
        const int r = tid >> 7;             // 0..7
        __shared__ float s_acc[8][EMB];
        float acc = 0.f;
#pragma unroll
        for (int k = 0; k < 5; k++) {
            const int p = j * 40 + r + k * 8;
            acc += CE[p * EMB + e];
        }
        s_acc[r][e] = acc;
        __syncthreads();
        if (r == 0) {
            float t = 0.f;
#pragma unroll
            for (int q = 0; q < 8; q++) t += s_acc[q][e];
            g_catpart[j * EMB + e] = t;
        }
    } else {
        // transpose, write-coalesced: out idx = w*EMB*EMB + i*EMB + o
        const int idx = (blockIdx.x - NCATBLK) * 1024 + tid;  // < 3*EMB*EMB
        const int w = idx / (EMB * EMB);
        const int rem = idx - w * (EMB * EMB);
        const int i = rem >> 7;
        const int o = rem & (EMB - 1);
        g_WT[idx] = CW[o * (EMB * 3) + i * 3 + w];
    }
}

// ---------------------------------------------------------------------------
// Kernel 2: fused (a) C-table build (blocks 0..99), (b) sentinel zero
//           (block 100), (c) sensitivity (block 101). 128 threads.
// ---------------------------------------------------------------------------
__global__ __launch_bounds__(EMB) void build_kernel(
    const float* __restrict__ PE,   // [NPRICE, EMB]
    const float* __restrict__ CB,   // conv bias [EMB]
    const float* __restrict__ GW,   // gate_w [EMB, 3*EMB]
    const float* __restrict__ GB,   // gate_b [EMB]
    float* __restrict__ sens_out)   // [EMB]
{
    const int o = threadIdx.x;
    if (blockIdx.x < NPRICE) {
        const int p = blockIdx.x;
        __shared__ float sE[EMB];
        sE[o] = PE[p * EMB + o];
        __syncthreads();
        float a0 = 0.f, a1 = 0.f, a2 = 0.f;
#pragma unroll 8
        for (int i = 0; i < EMB; i++) {
            const float e = sE[i];
            a0 = fmaf(e, g_WT[0 * (EMB * EMB) + i * EMB + o], a0);
            a1 = fmaf(e, g_WT[1 * (EMB * EMB) + i * EMB + o], a1);
            a2 = fmaf(e, g_WT[2 * (EMB * EMB) + i * EMB + o], a2);
        }
        g_C[(p * 3 + 0) * EMB + o] = a0;
        g_C[(p * 3 + 1) * EMB + o] = a1 + CB[o];   // bias folded into C1
        g_C[(p * 3 + 2) * EMB + o] = a2;
    } else if (blockIdx.x == NPRICE) {
        g_C[(NPRICE * 3 + 0) * EMB + o] = 0.f;
        g_C[(NPRICE * 3 + 1) * EMB + o] = 0.f;
        g_C[(NPRICE * 3 + 2) * EMB + o] = 0.f;
    } else {
        __shared__ float stats[3 * EMB];
        float s = 0.f, sq = 0.f;
#pragma unroll 10
        for (int p = 0; p < NPRICE; p++) {
            const float v = PE[p * EMB + o];
            s += v;
            sq = fmaf(v, v, sq);
        }
        const float mean = s * (1.f / NPRICE);
        float var = (sq - (float)NPRICE * mean * mean) * (1.f / (NPRICE - 1));
        var = fmaxf(var, 0.f);
        stats[o] = mean;
        stats[EMB + o] = sqrtf(var);

        float cs = 0.f;
#pragma unroll
        for (int j = 0; j < NCATBLK; j++) cs += g_catpart[j * EMB + o];
        stats[2 * EMB + o] = cs * (1.f / NCAT);
        __syncthreads();

        float acc = GB[o];
        const float* w = GW + o * (3 * EMB);
#pragma unroll 8
        for (int j = 0; j < 3 * EMB; j++) acc = fmaf(stats[j], w[j], acc);
        sens_out[o] = 1.f / (1.f + __expf(-acc));
    }
}

// ---------------------------------------------------------------------------
// Kernel 3: trend v3. Warp-per-row, lane owns 4 channels (float4),
// single-pass online softmax. grid = BATCH/4 CTAs x 128 threads.
// ---------------------------------------------------------------------------
__global__ __launch_bounds__(128) void trend_kernel(
    const int* __restrict__ seqs,         // [B, L] int32
    const int* __restrict__ mask,         // [B, L] int32
    const float* __restrict__ PE,         // [NPRICE, EMB]
    const float* __restrict__ AW,         // attn_w [1, EMB]
    float* __restrict__ trend)            // [B, EMB]
{
    const int warp = threadIdx.x >> 5;
    const int lane = threadIdx.x & 31;
    const int b = (blockIdx.x << 2) + warp;

    // byte offsets into g_C (idx * 1536), shifted with zero-row sentinels
    __shared__ int s_off[4][SEQL + 2];

    // ---- load indices + mask (lanes cover 50 entries in two strides) ----
    {
        int iv = seqs[b * SEQL + lane];
        iv = min(max(iv, 0), NPRICE - 1);
        s_off[warp][lane + 1] = iv * ROW_BYTES;
        if (lane < SEQL - 32) {
            int iv2 = seqs[b * SEQL + 32 + lane];
            iv2 = min(max(iv2, 0), NPRICE - 1);
            s_off[warp][lane + 33] = iv2 * ROW_BYTES;
        }
        if (lane == 0) {
            s_off[warp][0] = NPRICE * ROW_BYTES;
            s_off[warp][SEQL + 1] = NPRICE * ROW_BYTES;
        }
    }
    int mv = mask[b * SEQL + lane];
    if (lane < SEQL - 32) mv += mask[b * SEQL + 32 + lane];
#pragma unroll
    for (int off = 16; off; off >>= 1)
        mv += __shfl_xor_sync(0xffffffffu, mv, off);
    __syncwarp();

    float4* out4 = (float4*)(trend + (size_t)b * EMB) + lane;

    if (mv == 0) {
        *out4 = make_float4(0.f, 0.f, 0.f, 0.f);
        return;
    }
    if (mv < 3) {   // rare: mean pool over PE rows
        float4 acc = make_float4(0.f, 0.f, 0.f, 0.f);
        const char* PEb = (const char*)PE;
#pragma unroll 10
        for (int l = 0; l < SEQL; l++) {
            const int idx = s_off[warp][l + 1] / ROW_BYTES;
            const float4 v = *(const float4*)(PEb + (size_t)idx * (EMB * 4) + lane * 16);
            acc.x += v.x; acc.y += v.y; acc.z += v.z; acc.w += v.w;
        }
        const float s = 1.f / SEQL;
        *out4 = make_float4(acc.x * s, acc.y * s, acc.z * s, acc.w * s);
        return;
    }

    // ---- long branch: conv + relu + online-softmax attention pool ----
    const float4 aw4 = ((const float4*)AW)[lane];
    const char* Cb = (const char*)g_C;
    const int lo = lane * 16;

    float m = -1e30f, d = 0.f;
    float4 a = make_float4(0.f, 0.f, 0.f, 0.f);

    int o0 = s_off[warp][0];
    int o1 = s_off[warp][1];
#pragma unroll 10
    for (int l = 0; l < SEQL; l++) {
        const int o2 = s_off[warp][l + 2];
        const float4 c0 = *(const float4*)(Cb + o0 + lo);              // w=0
        const float4 c1 = *(const float4*)(Cb + o1 + 512 + lo);        // w=1 (+bias)
        const float4 c2 = *(const float4*)(Cb + o2 + 1024 + lo);       // w=2
        float4 r;
        r.x = fmaxf(c0.x + c1.x + c2.x, 0.f);
        r.y = fmaxf(c0.y + c1.y + c2.y, 0.f);
        r.z = fmaxf(c0.z + c1.z + c2.z, 0.f);
        r.w = fmaxf(c0.w + c1.w + c2.w, 0.f);

        float sp = r.x * aw4.x;
        sp = fmaf(r.y, aw4.y, sp);
        sp = fmaf(r.z, aw4.z, sp);
        sp = fmaf(r.w, aw4.w, sp);
#pragma unroll
        for (int off = 16; off; off >>= 1)
            sp += __shfl_xor_sync(0xffffffffu, sp, off);

        const float mn = fmaxf(m, sp);
        const float scale = __expf(m - mn);     // 0 on first iter, 1 when no new max
        const float w = __expf(sp - mn);
        d = fmaf(d, scale, w);
        a.x = fmaf(a.x, scale, r.x * w);
        a.y = fmaf(a.y, scale, r.y * w);
        a.z = fmaf(a.z, scale, r.z * w);
        a.w = fmaf(a.w, scale, r.w * w);
        m = mn;
        o0 = o1; o1 = o2;
    }

    const float inv = 1.f / d;
    *out4 = make_float4(a.x * inv, a.y * inv, a.z * inv, a.w * inv);
}

// ---------------------------------------------------------------------------
// launch
// ---------------------------------------------------------------------------
extern "C" void kernel_launch(void* const* d_in, const int* in_sizes, int n_in,
                              void* d_out, int out_size) {
    const float* price_emb  = (const float*)d_in[0];      // [100,128]
    const int*   price_seqs = (const int*)d_in[1];        // [4096,50] int32
    const float* cat_emb    = (const float*)d_in[2];      // [1000,128]
    const int*   sess_mask  = (const int*)d_in[3];        // [4096,50] int32
    const float* gate_w     = (const float*)d_in[4];      // [128,384]
    const float* gate_b     = (const float*)d_in[5];      // [128]
    const float* conv_w     = (const float*)d_in[6];      // [128,128,3]
    const float* conv_b     = (const float*)d_in[7];      // [128]
    const float* attn_w     = (const float*)d_in[8];      // [1,128]
    // attn_b (d_in[9]) cancels inside softmax — unused.

    float* out = (float*)d_out;
    float* sens_out  = out;          // first 128 floats
    float* trend_out = out + EMB;    // [4096,128]

    prep_kernel<<<NCATBLK + 48, 1024>>>(cat_emb, conv_w);
    build_kernel<<<NPRICE + 2, EMB>>>(price_emb, conv_b, gate_w, gate_b, sens_out);
    trend_kernel<<<BATCH / 4, 128>>>(price_seqs, sess_mask, price_emb,
                                     attn_w, trend_out);
}